// round 11
// baseline (speedup 1.0000x reference)
#include <cuda_runtime.h>

#define BSZ 32
#define Q   900
#define NCL 91
#define T   30
#define NT  (BSZ * T)   // 960

// ---------------------------------------------------------------------------
// Kernel 1: cost matrix. One block per (b,q) row. 128 threads.
//   C[row, j] = 5*L1(boxes) + (1 - softmax(logits)[tgt_label_j]) + 2*(1 - GIoU)
// ---------------------------------------------------------------------------
__global__ void __launch_bounds__(128) cost_kernel(
    const float* __restrict__ logits,   // [BSZ*Q, NCL]
    const float* __restrict__ pboxes,   // [BSZ*Q, 4]  cxcywh
    const int*   __restrict__ tlabels,  // [NT]
    const float* __restrict__ tboxes,   // [NT, 4]     cxcywh
    float* __restrict__ out)            // [BSZ*Q, NT]
{
    const int row = blockIdx.x;          // 0..BSZ*Q-1
    const int tid = threadIdx.x;         // 0..127

    __shared__ float probs[NCL];
    __shared__ float red[128];

    // --- softmax over 91 classes ---
    float l = (tid < NCL) ? logits[(size_t)row * NCL + tid] : -1e30f;
    red[tid] = l;
    __syncthreads();
    for (int s = 64; s > 0; s >>= 1) {
        if (tid < s) red[tid] = fmaxf(red[tid], red[tid + s]);
        __syncthreads();
    }
    const float mx = red[0];
    __syncthreads();
    float e = (tid < NCL) ? expf(l - mx) : 0.0f;
    red[tid] = e;
    __syncthreads();
    for (int s = 64; s > 0; s >>= 1) {
        if (tid < s) red[tid] += red[tid + s];
        __syncthreads();
    }
    const float sum = red[0];
    if (tid < NCL) probs[tid] = e / sum;
    __syncthreads();

    // --- query box ---
    const float4 qb = reinterpret_cast<const float4*>(pboxes)[row];
    const float qx0 = qb.x - 0.5f * qb.z, qy0 = qb.y - 0.5f * qb.w;
    const float qx1 = qb.x + 0.5f * qb.z, qy1 = qb.y + 0.5f * qb.w;
    const float areaA = (qx1 - qx0) * (qy1 - qy0);

    float* orow = out + (size_t)row * NT;

    for (int j = tid; j < NT; j += 128) {
        const float4 tb = reinterpret_cast<const float4*>(tboxes)[j];
        const int lab = tlabels[j];

        const float cb = fabsf(qb.x - tb.x) + fabsf(qb.y - tb.y) +
                         fabsf(qb.z - tb.z) + fabsf(qb.w - tb.w);

        const float tx0 = tb.x - 0.5f * tb.z, ty0 = tb.y - 0.5f * tb.w;
        const float tx1 = tb.x + 0.5f * tb.z, ty1 = tb.y + 0.5f * tb.w;
        const float areaB = (tx1 - tx0) * (ty1 - ty0);

        const float ltx = fmaxf(qx0, tx0), lty = fmaxf(qy0, ty0);
        const float rbx = fminf(qx1, tx1), rby = fminf(qy1, ty1);
        const float iw = fmaxf(rbx - ltx, 0.0f), ih = fmaxf(rby - lty, 0.0f);
        const float inter = iw * ih;
        const float uni = areaA + areaB - inter;
        const float iou = inter / uni;

        const float ex0 = fminf(qx0, tx0), ey0 = fminf(qy0, ty0);
        const float ex1 = fmaxf(qx1, tx1), ey1 = fmaxf(qy1, ty1);
        const float encl = (ex1 - ex0) * (ey1 - ey0);
        const float giou = iou - (encl - uni) / encl;

        orow[j] = 5.0f * cb + (1.0f - probs[lab]) + 2.0f * (1.0f - giou);
    }
}

// ---------------------------------------------------------------------------
// Kernel 2: Jonker-Volgenant LSA (exact replica of the reference's float64
// algorithm), one block per batch. costT[t][q] = C3[b, q, b*T + t].
// Dynamic shared: costT fp32 + dual/aux arrays (double).
// ---------------------------------------------------------------------------
__global__ void __launch_bounds__(256) lsa_kernel(float* __restrict__ C3out)
{
    const int b = blockIdx.x;
    const int tid = threadIdx.x;
    const double INF = 1e18;

    extern __shared__ unsigned char smraw[];
    float*  costT = (float*)smraw;                          // T*Q floats = 108000 B
    double* v     = (double*)(smraw + (size_t)T * Q * 4);   // Q+1
    double* minv  = v + (Q + 1);                            // Q+1
    double* rval  = minv + (Q + 1);                         // 256
    int*    p     = (int*)(rval + 256);                     // Q+1
    int*    way   = p + (Q + 1);                            // Q+1
    int*    used  = way + (Q + 1);                          // Q+1
    int*    ridx  = used + (Q + 1);                         // 256

    __shared__ double u[T + 1];
    __shared__ int s_j0, s_i0, s_j1, s_done;
    __shared__ double s_delta;

    // Load transposed cost slice: costT[t*Q + q] = C3[b, q, b*T + t]
    const float* Cb = C3out + ((size_t)b * Q) * NT + (size_t)b * T;
    for (int idx = tid; idx < Q * T; idx += 256) {
        int q = idx / T;
        int t = idx - q * T;
        costT[t * Q + q] = Cb[(size_t)q * NT + t];
    }
    for (int j = tid; j <= Q; j += 256) { v[j] = 0.0; p[j] = 0; }
    if (tid <= T) u[tid] = 0.0;
    __syncthreads();

    for (int i = 1; i <= T; ++i) {
        for (int j = tid; j <= Q; j += 256) { minv[j] = INF; used[j] = 0; }
        if (tid == 0) { p[0] = i; s_j0 = 0; }
        __syncthreads();

        while (true) {
            if (tid == 0) { used[s_j0] = 1; s_i0 = p[s_j0]; }
            __syncthreads();
            const int j0 = s_j0;
            const int i0 = s_i0;
            const double ui0 = u[i0];
            const float* crow = costT + (i0 - 1) * Q;

            // relax + local argmin (each thread owns its columns)
            double bv = INF;
            int bj = Q + 2;
            for (int j = tid + 1; j <= Q; j += 256) {
                if (!used[j]) {
                    double cur = (double)crow[j - 1] - ui0 - v[j];
                    if (cur < minv[j]) { minv[j] = cur; way[j] = j0; }
                    double mv = minv[j];
                    if (mv < bv) { bv = mv; bj = j; }
                }
            }
            rval[tid] = bv; ridx[tid] = bj;
            __syncthreads();

            // block argmin, tie -> smaller index (matches np.argmin)
            for (int s = 128; s > 0; s >>= 1) {
                if (tid < s) {
                    double ov = rval[tid + s]; int oj = ridx[tid + s];
                    if (ov < rval[tid] || (ov == rval[tid] && oj < ridx[tid])) {
                        rval[tid] = ov; ridx[tid] = oj;
                    }
                }
                __syncthreads();
            }
            if (tid == 0) { s_delta = rval[0]; s_j1 = ridx[0]; }
            __syncthreads();
            const double delta = s_delta;
            const int j1 = s_j1;

            // dual update (used j: distinct p[j] -> race-free)
            for (int j = tid; j <= Q; j += 256) {
                if (used[j]) { v[j] -= delta; u[p[j]] += delta; }
                else if (j >= 1) minv[j] -= delta;
            }
            if (tid == 0) { s_j0 = j1; s_done = (p[j1] == 0); }
            __syncthreads();
            if (s_done) break;
        }

        // augment (thread 0; 'way' reads complete before next row writes it,
        // ordered by the next row's post-init __syncthreads)
        if (tid == 0) {
            int j0 = s_j0;
            while (j0) { int jn = way[j0]; p[j0] = p[jn]; j0 = jn; }
        }
    }
    __syncthreads();

    if (tid == 0) {
        int preds[T], tg[T];
        for (int j = 1; j <= Q; ++j) {
            int pj = p[j];
            if (pj > 0) preds[pj - 1] = j - 1;
        }
        for (int t = 0; t < T; ++t) tg[t] = t;
        // stable insertion sort by pred index ascending
        for (int a = 1; a < T; ++a) {
            int pv = preds[a], tv = tg[a];
            int c = a - 1;
            while (c >= 0 && preds[c] > pv) {
                preds[c + 1] = preds[c]; tg[c + 1] = tg[c]; --c;
            }
            preds[c + 1] = pv; tg[c + 1] = tv;
        }
        const size_t base = (size_t)BSZ * Q * NT;
        for (int k = 0; k < T; ++k) {
            C3out[base + (size_t)b * T + k]                    = (float)preds[k];
            C3out[base + (size_t)BSZ * T + (size_t)b * T + k]  = (float)tg[k];
        }
    }
}

// ---------------------------------------------------------------------------
extern "C" void kernel_launch(void* const* d_in, const int* in_sizes, int n_in,
                              void* d_out, int out_size)
{
    const float* logits  = (const float*)d_in[0];   // [32,900,91]
    const float* pboxes  = (const float*)d_in[1];   // [32,900,4]
    const int*   tlabels = (const int*)  d_in[2];   // [32,30]
    const float* tboxes  = (const float*)d_in[3];   // [32,30,4]
    float* out = (float*)d_out;

    cost_kernel<<<BSZ * Q, 128>>>(logits, pboxes, tlabels, tboxes, out);

    const size_t smem =
        (size_t)T * Q * sizeof(float)            // costT   108000
        + (Q + 1) * sizeof(double) * 2           // v, minv  14416
        + 256 * sizeof(double)                   // rval      2048
        + (Q + 1) * sizeof(int) * 3              // p,way,used 10812
        + 256 * sizeof(int);                     // ridx      1024
    cudaFuncSetAttribute(lsa_kernel, cudaFuncAttributeMaxDynamicSharedMemorySize,
                         (int)smem);
    lsa_kernel<<<BSZ, 256, smem>>>(out);
}

// round 12
// speedup vs baseline: 1.0001x; 1.0001x over previous
#include <cuda_runtime.h>

#define BSZ 32
#define Q   900
#define NCL 91
#define T   30
#define NT  (BSZ * T)   // 960

// ---------------------------------------------------------------------------
// Kernel 1: cost matrix. One block per (b,q) row. 128 threads.
//   C[row, j] = 5*L1(boxes) + (1 - softmax(logits)[tgt_label_j]) + 2*(1 - GIoU)
// ---------------------------------------------------------------------------
__global__ void __launch_bounds__(128) cost_kernel(
    const float* __restrict__ logits,   // [BSZ*Q, NCL]
    const float* __restrict__ pboxes,   // [BSZ*Q, 4]  cxcywh
    const int*   __restrict__ tlabels,  // [NT]
    const float* __restrict__ tboxes,   // [NT, 4]     cxcywh
    float* __restrict__ out)            // [BSZ*Q, NT]
{
    const int row = blockIdx.x;          // 0..BSZ*Q-1
    const int tid = threadIdx.x;         // 0..127

    __shared__ float probs[NCL];
    __shared__ float red[128];

    // --- softmax over 91 classes ---
    float l = (tid < NCL) ? logits[(size_t)row * NCL + tid] : -1e30f;
    red[tid] = l;
    __syncthreads();
    for (int s = 64; s > 0; s >>= 1) {
        if (tid < s) red[tid] = fmaxf(red[tid], red[tid + s]);
        __syncthreads();
    }
    const float mx = red[0];
    __syncthreads();
    float e = (tid < NCL) ? expf(l - mx) : 0.0f;
    red[tid] = e;
    __syncthreads();
    for (int s = 64; s > 0; s >>= 1) {
        if (tid < s) red[tid] += red[tid + s];
        __syncthreads();
    }
    const float sum = red[0];
    if (tid < NCL) probs[tid] = e / sum;
    __syncthreads();

    // --- query box ---
    const float4 qb = reinterpret_cast<const float4*>(pboxes)[row];
    const float qx0 = qb.x - 0.5f * qb.z, qy0 = qb.y - 0.5f * qb.w;
    const float qx1 = qb.x + 0.5f * qb.z, qy1 = qb.y + 0.5f * qb.w;
    const float areaA = (qx1 - qx0) * (qy1 - qy0);

    float* orow = out + (size_t)row * NT;

    for (int j = tid; j < NT; j += 128) {
        const float4 tb = reinterpret_cast<const float4*>(tboxes)[j];
        const int lab = tlabels[j];

        const float cb = fabsf(qb.x - tb.x) + fabsf(qb.y - tb.y) +
                         fabsf(qb.z - tb.z) + fabsf(qb.w - tb.w);

        const float tx0 = tb.x - 0.5f * tb.z, ty0 = tb.y - 0.5f * tb.w;
        const float tx1 = tb.x + 0.5f * tb.z, ty1 = tb.y + 0.5f * tb.w;
        const float areaB = (tx1 - tx0) * (ty1 - ty0);

        const float ltx = fmaxf(qx0, tx0), lty = fmaxf(qy0, ty0);
        const float rbx = fminf(qx1, tx1), rby = fminf(qy1, ty1);
        const float iw = fmaxf(rbx - ltx, 0.0f), ih = fmaxf(rby - lty, 0.0f);
        const float inter = iw * ih;
        const float uni = areaA + areaB - inter;
        const float iou = inter / uni;

        const float ex0 = fminf(qx0, tx0), ey0 = fminf(qy0, ty0);
        const float ex1 = fmaxf(qx1, tx1), ey1 = fmaxf(qy1, ty1);
        const float encl = (ex1 - ex0) * (ey1 - ey0);
        const float giou = iou - (encl - uni) / encl;

        orow[j] = 5.0f * cb + (1.0f - probs[lab]) + 2.0f * (1.0f - giou);
    }
}

// ---------------------------------------------------------------------------
// Kernel 2: Jonker-Volgenant LSA (exact replica of the reference's float64
// algorithm), one block per batch. costT[t][q] = C3[b, q, b*T + t].
// Dynamic shared: costT fp32 + dual/aux arrays (double).
// ---------------------------------------------------------------------------
__global__ void __launch_bounds__(256) lsa_kernel(float* __restrict__ C3out)
{
    const int b = blockIdx.x;
    const int tid = threadIdx.x;
    const double INF = 1e18;

    extern __shared__ unsigned char smraw[];
    float*  costT = (float*)smraw;                          // T*Q floats = 108000 B
    double* v     = (double*)(smraw + (size_t)T * Q * 4);   // Q+1
    double* minv  = v + (Q + 1);                            // Q+1
    double* rval  = minv + (Q + 1);                         // 256
    int*    p     = (int*)(rval + 256);                     // Q+1
    int*    way   = p + (Q + 1);                            // Q+1
    int*    used  = way + (Q + 1);                          // Q+1
    int*    ridx  = used + (Q + 1);                         // 256

    __shared__ double u[T + 1];
    __shared__ int s_j0, s_i0, s_j1, s_done;
    __shared__ double s_delta;

    // Load transposed cost slice: costT[t*Q + q] = C3[b, q, b*T + t]
    const float* Cb = C3out + ((size_t)b * Q) * NT + (size_t)b * T;
    for (int idx = tid; idx < Q * T; idx += 256) {
        int q = idx / T;
        int t = idx - q * T;
        costT[t * Q + q] = Cb[(size_t)q * NT + t];
    }
    for (int j = tid; j <= Q; j += 256) { v[j] = 0.0; p[j] = 0; }
    if (tid <= T) u[tid] = 0.0;
    __syncthreads();

    for (int i = 1; i <= T; ++i) {
        for (int j = tid; j <= Q; j += 256) { minv[j] = INF; used[j] = 0; }
        if (tid == 0) { p[0] = i; s_j0 = 0; }
        __syncthreads();

        while (true) {
            if (tid == 0) { used[s_j0] = 1; s_i0 = p[s_j0]; }
            __syncthreads();
            const int j0 = s_j0;
            const int i0 = s_i0;
            const double ui0 = u[i0];
            const float* crow = costT + (i0 - 1) * Q;

            // relax + local argmin (each thread owns its columns)
            double bv = INF;
            int bj = Q + 2;
            for (int j = tid + 1; j <= Q; j += 256) {
                if (!used[j]) {
                    double cur = (double)crow[j - 1] - ui0 - v[j];
                    if (cur < minv[j]) { minv[j] = cur; way[j] = j0; }
                    double mv = minv[j];
                    if (mv < bv) { bv = mv; bj = j; }
                }
            }
            rval[tid] = bv; ridx[tid] = bj;
            __syncthreads();

            // block argmin, tie -> smaller index (matches np.argmin)
            for (int s = 128; s > 0; s >>= 1) {
                if (tid < s) {
                    double ov = rval[tid + s]; int oj = ridx[tid + s];
                    if (ov < rval[tid] || (ov == rval[tid] && oj < ridx[tid])) {
                        rval[tid] = ov; ridx[tid] = oj;
                    }
                }
                __syncthreads();
            }
            if (tid == 0) { s_delta = rval[0]; s_j1 = ridx[0]; }
            __syncthreads();
            const double delta = s_delta;
            const int j1 = s_j1;

            // dual update (used j: distinct p[j] -> race-free)
            for (int j = tid; j <= Q; j += 256) {
                if (used[j]) { v[j] -= delta; u[p[j]] += delta; }
                else if (j >= 1) minv[j] -= delta;
            }
            if (tid == 0) { s_j0 = j1; s_done = (p[j1] == 0); }
            __syncthreads();
            if (s_done) break;
        }

        // augment (thread 0; 'way' reads complete before next row writes it,
        // ordered by the next row's post-init __syncthreads)
        if (tid == 0) {
            int j0 = s_j0;
            while (j0) { int jn = way[j0]; p[j0] = p[jn]; j0 = jn; }
        }
    }
    __syncthreads();

    if (tid == 0) {
        int preds[T], tg[T];
        for (int j = 1; j <= Q; ++j) {
            int pj = p[j];
            if (pj > 0) preds[pj - 1] = j - 1;
        }
        for (int t = 0; t < T; ++t) tg[t] = t;
        // stable insertion sort by pred index ascending
        for (int a = 1; a < T; ++a) {
            int pv = preds[a], tv = tg[a];
            int c = a - 1;
            while (c >= 0 && preds[c] > pv) {
                preds[c + 1] = preds[c]; tg[c + 1] = tg[c]; --c;
            }
            preds[c + 1] = pv; tg[c + 1] = tv;
        }
        const size_t base = (size_t)BSZ * Q * NT;
        for (int k = 0; k < T; ++k) {
            C3out[base + (size_t)b * T + k]                    = (float)preds[k];
            C3out[base + (size_t)BSZ * T + (size_t)b * T + k]  = (float)tg[k];
        }
    }
}

// ---------------------------------------------------------------------------
extern "C" void kernel_launch(void* const* d_in, const int* in_sizes, int n_in,
                              void* d_out, int out_size)
{
    const float* logits  = (const float*)d_in[0];   // [32,900,91]
    const float* pboxes  = (const float*)d_in[1];   // [32,900,4]
    const int*   tlabels = (const int*)  d_in[2];   // [32,30]
    const float* tboxes  = (const float*)d_in[3];   // [32,30,4]
    float* out = (float*)d_out;

    cost_kernel<<<BSZ * Q, 128>>>(logits, pboxes, tlabels, tboxes, out);

    const size_t smem =
        (size_t)T * Q * sizeof(float)            // costT   108000
        + (Q + 1) * sizeof(double) * 2           // v, minv  14416
        + 256 * sizeof(double)                   // rval      2048
        + (Q + 1) * sizeof(int) * 3              // p,way,used 10812
        + 256 * sizeof(int);                     // ridx      1024
    cudaFuncSetAttribute(lsa_kernel, cudaFuncAttributeMaxDynamicSharedMemorySize,
                         (int)smem);
    lsa_kernel<<<BSZ, 256, smem>>>(out);
}

// round 13
// speedup vs baseline: 1.0024x; 1.0022x over previous
#include <cuda_runtime.h>

#define BSZ 32
#define Q   900
#define NCL 91
#define T   30
#define NT  (BSZ * T)   // 960

// ---------------------------------------------------------------------------
// Kernel 1: cost matrix. One block per (b,q) row. 128 threads.
//   C[row, j] = 5*L1(boxes) + (1 - softmax(logits)[tgt_label_j]) + 2*(1 - GIoU)
// ---------------------------------------------------------------------------
__global__ void __launch_bounds__(128) cost_kernel(
    const float* __restrict__ logits,   // [BSZ*Q, NCL]
    const float* __restrict__ pboxes,   // [BSZ*Q, 4]  cxcywh
    const int*   __restrict__ tlabels,  // [NT]
    const float* __restrict__ tboxes,   // [NT, 4]     cxcywh
    float* __restrict__ out)            // [BSZ*Q, NT]
{
    const int row = blockIdx.x;          // 0..BSZ*Q-1
    const int tid = threadIdx.x;         // 0..127

    __shared__ float probs[NCL];
    __shared__ float red[128];

    // --- softmax over 91 classes ---
    float l = (tid < NCL) ? logits[(size_t)row * NCL + tid] : -1e30f;
    red[tid] = l;
    __syncthreads();
    for (int s = 64; s > 0; s >>= 1) {
        if (tid < s) red[tid] = fmaxf(red[tid], red[tid + s]);
        __syncthreads();
    }
    const float mx = red[0];
    __syncthreads();
    float e = (tid < NCL) ? expf(l - mx) : 0.0f;
    red[tid] = e;
    __syncthreads();
    for (int s = 64; s > 0; s >>= 1) {
        if (tid < s) red[tid] += red[tid + s];
        __syncthreads();
    }
    const float sum = red[0];
    if (tid < NCL) probs[tid] = e / sum;
    __syncthreads();

    // --- query box ---
    const float4 qb = reinterpret_cast<const float4*>(pboxes)[row];
    const float qx0 = qb.x - 0.5f * qb.z, qy0 = qb.y - 0.5f * qb.w;
    const float qx1 = qb.x + 0.5f * qb.z, qy1 = qb.y + 0.5f * qb.w;
    const float areaA = (qx1 - qx0) * (qy1 - qy0);

    float* orow = out + (size_t)row * NT;

    for (int j = tid; j < NT; j += 128) {
        const float4 tb = reinterpret_cast<const float4*>(tboxes)[j];
        const int lab = tlabels[j];

        const float cb = fabsf(qb.x - tb.x) + fabsf(qb.y - tb.y) +
                         fabsf(qb.z - tb.z) + fabsf(qb.w - tb.w);

        const float tx0 = tb.x - 0.5f * tb.z, ty0 = tb.y - 0.5f * tb.w;
        const float tx1 = tb.x + 0.5f * tb.z, ty1 = tb.y + 0.5f * tb.w;
        const float areaB = (tx1 - tx0) * (ty1 - ty0);

        const float ltx = fmaxf(qx0, tx0), lty = fmaxf(qy0, ty0);
        const float rbx = fminf(qx1, tx1), rby = fminf(qy1, ty1);
        const float iw = fmaxf(rbx - ltx, 0.0f), ih = fmaxf(rby - lty, 0.0f);
        const float inter = iw * ih;
        const float uni = areaA + areaB - inter;
        const float iou = inter / uni;

        const float ex0 = fminf(qx0, tx0), ey0 = fminf(qy0, ty0);
        const float ex1 = fmaxf(qx1, tx1), ey1 = fmaxf(qy1, ty1);
        const float encl = (ex1 - ex0) * (ey1 - ey0);
        const float giou = iou - (encl - uni) / encl;

        orow[j] = 5.0f * cb + (1.0f - probs[lab]) + 2.0f * (1.0f - giou);
    }
}

// ---------------------------------------------------------------------------
// Kernel 2: Jonker-Volgenant LSA (exact replica of the reference's float64
// algorithm), one block per batch. costT[t][q] = C3[b, q, b*T + t].
// Dynamic shared: costT fp32 + dual/aux arrays (double).
// ---------------------------------------------------------------------------
__global__ void __launch_bounds__(256) lsa_kernel(float* __restrict__ C3out)
{
    const int b = blockIdx.x;
    const int tid = threadIdx.x;
    const double INF = 1e18;

    extern __shared__ unsigned char smraw[];
    float*  costT = (float*)smraw;                          // T*Q floats = 108000 B
    double* v     = (double*)(smraw + (size_t)T * Q * 4);   // Q+1
    double* minv  = v + (Q + 1);                            // Q+1
    double* rval  = minv + (Q + 1);                         // 256
    int*    p     = (int*)(rval + 256);                     // Q+1
    int*    way   = p + (Q + 1);                            // Q+1
    int*    used  = way + (Q + 1);                          // Q+1
    int*    ridx  = used + (Q + 1);                         // 256

    __shared__ double u[T + 1];
    __shared__ int s_j0, s_i0, s_j1, s_done;
    __shared__ double s_delta;

    // Load transposed cost slice: costT[t*Q + q] = C3[b, q, b*T + t]
    const float* Cb = C3out + ((size_t)b * Q) * NT + (size_t)b * T;
    for (int idx = tid; idx < Q * T; idx += 256) {
        int q = idx / T;
        int t = idx - q * T;
        costT[t * Q + q] = Cb[(size_t)q * NT + t];
    }
    for (int j = tid; j <= Q; j += 256) { v[j] = 0.0; p[j] = 0; }
    if (tid <= T) u[tid] = 0.0;
    __syncthreads();

    for (int i = 1; i <= T; ++i) {
        for (int j = tid; j <= Q; j += 256) { minv[j] = INF; used[j] = 0; }
        if (tid == 0) { p[0] = i; s_j0 = 0; }
        __syncthreads();

        while (true) {
            if (tid == 0) { used[s_j0] = 1; s_i0 = p[s_j0]; }
            __syncthreads();
            const int j0 = s_j0;
            const int i0 = s_i0;
            const double ui0 = u[i0];
            const float* crow = costT + (i0 - 1) * Q;

            // relax + local argmin (each thread owns its columns)
            double bv = INF;
            int bj = Q + 2;
            for (int j = tid + 1; j <= Q; j += 256) {
                if (!used[j]) {
                    double cur = (double)crow[j - 1] - ui0 - v[j];
                    if (cur < minv[j]) { minv[j] = cur; way[j] = j0; }
                    double mv = minv[j];
                    if (mv < bv) { bv = mv; bj = j; }
                }
            }
            rval[tid] = bv; ridx[tid] = bj;
            __syncthreads();

            // block argmin, tie -> smaller index (matches np.argmin)
            for (int s = 128; s > 0; s >>= 1) {
                if (tid < s) {
                    double ov = rval[tid + s]; int oj = ridx[tid + s];
                    if (ov < rval[tid] || (ov == rval[tid] && oj < ridx[tid])) {
                        rval[tid] = ov; ridx[tid] = oj;
                    }
                }
                __syncthreads();
            }
            if (tid == 0) { s_delta = rval[0]; s_j1 = ridx[0]; }
            __syncthreads();
            const double delta = s_delta;
            const int j1 = s_j1;

            // dual update (used j: distinct p[j] -> race-free)
            for (int j = tid; j <= Q; j += 256) {
                if (used[j]) { v[j] -= delta; u[p[j]] += delta; }
                else if (j >= 1) minv[j] -= delta;
            }
            if (tid == 0) { s_j0 = j1; s_done = (p[j1] == 0); }
            __syncthreads();
            if (s_done) break;
        }

        // augment (thread 0; 'way' reads complete before next row writes it,
        // ordered by the next row's post-init __syncthreads)
        if (tid == 0) {
            int j0 = s_j0;
            while (j0) { int jn = way[j0]; p[j0] = p[jn]; j0 = jn; }
        }
    }
    __syncthreads();

    if (tid == 0) {
        int preds[T], tg[T];
        for (int j = 1; j <= Q; ++j) {
            int pj = p[j];
            if (pj > 0) preds[pj - 1] = j - 1;
        }
        for (int t = 0; t < T; ++t) tg[t] = t;
        // stable insertion sort by pred index ascending
        for (int a = 1; a < T; ++a) {
            int pv = preds[a], tv = tg[a];
            int c = a - 1;
            while (c >= 0 && preds[c] > pv) {
                preds[c + 1] = preds[c]; tg[c + 1] = tg[c]; --c;
            }
            preds[c + 1] = pv; tg[c + 1] = tv;
        }
        const size_t base = (size_t)BSZ * Q * NT;
        for (int k = 0; k < T; ++k) {
            C3out[base + (size_t)b * T + k]                    = (float)preds[k];
            C3out[base + (size_t)BSZ * T + (size_t)b * T + k]  = (float)tg[k];
        }
    }
}

// ---------------------------------------------------------------------------
extern "C" void kernel_launch(void* const* d_in, const int* in_sizes, int n_in,
                              void* d_out, int out_size)
{
    const float* logits  = (const float*)d_in[0];   // [32,900,91]
    const float* pboxes  = (const float*)d_in[1];   // [32,900,4]
    const int*   tlabels = (const int*)  d_in[2];   // [32,30]
    const float* tboxes  = (const float*)d_in[3];   // [32,30,4]
    float* out = (float*)d_out;

    cost_kernel<<<BSZ * Q, 128>>>(logits, pboxes, tlabels, tboxes, out);

    const size_t smem =
        (size_t)T * Q * sizeof(float)            // costT   108000
        + (Q + 1) * sizeof(double) * 2           // v, minv  14416
        + 256 * sizeof(double)                   // rval      2048
        + (Q + 1) * sizeof(int) * 3              // p,way,used 10812
        + 256 * sizeof(int);                     // ridx      1024
    cudaFuncSetAttribute(lsa_kernel, cudaFuncAttributeMaxDynamicSharedMemorySize,
                         (int)smem);
    lsa_kernel<<<BSZ, 256, smem>>>(out);
}

// round 14
// speedup vs baseline: 1.0025x; 1.0001x over previous
#include <cuda_runtime.h>

#define BSZ 32
#define Q   900
#define NCL 91
#define T   30
#define NT  (BSZ * T)   // 960

// ---------------------------------------------------------------------------
// Kernel 1: cost matrix. One block per (b,q) row. 128 threads.
//   C[row, j] = 5*L1(boxes) + (1 - softmax(logits)[tgt_label_j]) + 2*(1 - GIoU)
// ---------------------------------------------------------------------------
__global__ void __launch_bounds__(128) cost_kernel(
    const float* __restrict__ logits,   // [BSZ*Q, NCL]
    const float* __restrict__ pboxes,   // [BSZ*Q, 4]  cxcywh
    const int*   __restrict__ tlabels,  // [NT]
    const float* __restrict__ tboxes,   // [NT, 4]     cxcywh
    float* __restrict__ out)            // [BSZ*Q, NT]
{
    const int row = blockIdx.x;          // 0..BSZ*Q-1
    const int tid = threadIdx.x;         // 0..127

    __shared__ float probs[NCL];
    __shared__ float red[128];

    // --- softmax over 91 classes ---
    float l = (tid < NCL) ? logits[(size_t)row * NCL + tid] : -1e30f;
    red[tid] = l;
    __syncthreads();
    for (int s = 64; s > 0; s >>= 1) {
        if (tid < s) red[tid] = fmaxf(red[tid], red[tid + s]);
        __syncthreads();
    }
    const float mx = red[0];
    __syncthreads();
    float e = (tid < NCL) ? expf(l - mx) : 0.0f;
    red[tid] = e;
    __syncthreads();
    for (int s = 64; s > 0; s >>= 1) {
        if (tid < s) red[tid] += red[tid + s];
        __syncthreads();
    }
    const float sum = red[0];
    if (tid < NCL) probs[tid] = e / sum;
    __syncthreads();

    // --- query box ---
    const float4 qb = reinterpret_cast<const float4*>(pboxes)[row];
    const float qx0 = qb.x - 0.5f * qb.z, qy0 = qb.y - 0.5f * qb.w;
    const float qx1 = qb.x + 0.5f * qb.z, qy1 = qb.y + 0.5f * qb.w;
    const float areaA = (qx1 - qx0) * (qy1 - qy0);

    float* orow = out + (size_t)row * NT;

    for (int j = tid; j < NT; j += 128) {
        const float4 tb = reinterpret_cast<const float4*>(tboxes)[j];
        const int lab = tlabels[j];

        const float cb = fabsf(qb.x - tb.x) + fabsf(qb.y - tb.y) +
                         fabsf(qb.z - tb.z) + fabsf(qb.w - tb.w);

        const float tx0 = tb.x - 0.5f * tb.z, ty0 = tb.y - 0.5f * tb.w;
        const float tx1 = tb.x + 0.5f * tb.z, ty1 = tb.y + 0.5f * tb.w;
        const float areaB = (tx1 - tx0) * (ty1 - ty0);

        const float ltx = fmaxf(qx0, tx0), lty = fmaxf(qy0, ty0);
        const float rbx = fminf(qx1, tx1), rby = fminf(qy1, ty1);
        const float iw = fmaxf(rbx - ltx, 0.0f), ih = fmaxf(rby - lty, 0.0f);
        const float inter = iw * ih;
        const float uni = areaA + areaB - inter;
        const float iou = inter / uni;

        const float ex0 = fminf(qx0, tx0), ey0 = fminf(qy0, ty0);
        const float ex1 = fmaxf(qx1, tx1), ey1 = fmaxf(qy1, ty1);
        const float encl = (ex1 - ex0) * (ey1 - ey0);
        const float giou = iou - (encl - uni) / encl;

        orow[j] = 5.0f * cb + (1.0f - probs[lab]) + 2.0f * (1.0f - giou);
    }
}

// ---------------------------------------------------------------------------
// Kernel 2: Jonker-Volgenant LSA (exact replica of the reference's float64
// algorithm), one block per batch. costT[t][q] = C3[b, q, b*T + t].
// Dynamic shared: costT fp32 + dual/aux arrays (double).
// ---------------------------------------------------------------------------
__global__ void __launch_bounds__(256) lsa_kernel(float* __restrict__ C3out)
{
    const int b = blockIdx.x;
    const int tid = threadIdx.x;
    const double INF = 1e18;

    extern __shared__ unsigned char smraw[];
    float*  costT = (float*)smraw;                          // T*Q floats = 108000 B
    double* v     = (double*)(smraw + (size_t)T * Q * 4);   // Q+1
    double* minv  = v + (Q + 1);                            // Q+1
    double* rval  = minv + (Q + 1);                         // 256
    int*    p     = (int*)(rval + 256);                     // Q+1
    int*    way   = p + (Q + 1);                            // Q+1
    int*    used  = way + (Q + 1);                          // Q+1
    int*    ridx  = used + (Q + 1);                         // 256

    __shared__ double u[T + 1];
    __shared__ int s_j0, s_i0, s_j1, s_done;
    __shared__ double s_delta;

    // Load transposed cost slice: costT[t*Q + q] = C3[b, q, b*T + t]
    const float* Cb = C3out + ((size_t)b * Q) * NT + (size_t)b * T;
    for (int idx = tid; idx < Q * T; idx += 256) {
        int q = idx / T;
        int t = idx - q * T;
        costT[t * Q + q] = Cb[(size_t)q * NT + t];
    }
    for (int j = tid; j <= Q; j += 256) { v[j] = 0.0; p[j] = 0; }
    if (tid <= T) u[tid] = 0.0;
    __syncthreads();

    for (int i = 1; i <= T; ++i) {
        for (int j = tid; j <= Q; j += 256) { minv[j] = INF; used[j] = 0; }
        if (tid == 0) { p[0] = i; s_j0 = 0; }
        __syncthreads();

        while (true) {
            if (tid == 0) { used[s_j0] = 1; s_i0 = p[s_j0]; }
            __syncthreads();
            const int j0 = s_j0;
            const int i0 = s_i0;
            const double ui0 = u[i0];
            const float* crow = costT + (i0 - 1) * Q;

            // relax + local argmin (each thread owns its columns)
            double bv = INF;
            int bj = Q + 2;
            for (int j = tid + 1; j <= Q; j += 256) {
                if (!used[j]) {
                    double cur = (double)crow[j - 1] - ui0 - v[j];
                    if (cur < minv[j]) { minv[j] = cur; way[j] = j0; }
                    double mv = minv[j];
                    if (mv < bv) { bv = mv; bj = j; }
                }
            }
            rval[tid] = bv; ridx[tid] = bj;
            __syncthreads();

            // block argmin, tie -> smaller index (matches np.argmin)
            for (int s = 128; s > 0; s >>= 1) {
                if (tid < s) {
                    double ov = rval[tid + s]; int oj = ridx[tid + s];
                    if (ov < rval[tid] || (ov == rval[tid] && oj < ridx[tid])) {
                        rval[tid] = ov; ridx[tid] = oj;
                    }
                }
                __syncthreads();
            }
            if (tid == 0) { s_delta = rval[0]; s_j1 = ridx[0]; }
            __syncthreads();
            const double delta = s_delta;
            const int j1 = s_j1;

            // dual update (used j: distinct p[j] -> race-free)
            for (int j = tid; j <= Q; j += 256) {
                if (used[j]) { v[j] -= delta; u[p[j]] += delta; }
                else if (j >= 1) minv[j] -= delta;
            }
            if (tid == 0) { s_j0 = j1; s_done = (p[j1] == 0); }
            __syncthreads();
            if (s_done) break;
        }

        // augment (thread 0; 'way' reads complete before next row writes it,
        // ordered by the next row's post-init __syncthreads)
        if (tid == 0) {
            int j0 = s_j0;
            while (j0) { int jn = way[j0]; p[j0] = p[jn]; j0 = jn; }
        }
    }
    __syncthreads();

    if (tid == 0) {
        int preds[T], tg[T];
        for (int j = 1; j <= Q; ++j) {
            int pj = p[j];
            if (pj > 0) preds[pj - 1] = j - 1;
        }
        for (int t = 0; t < T; ++t) tg[t] = t;
        // stable insertion sort by pred index ascending
        for (int a = 1; a < T; ++a) {
            int pv = preds[a], tv = tg[a];
            int c = a - 1;
            while (c >= 0 && preds[c] > pv) {
                preds[c + 1] = preds[c]; tg[c + 1] = tg[c]; --c;
            }
            preds[c + 1] = pv; tg[c + 1] = tv;
        }
        const size_t base = (size_t)BSZ * Q * NT;
        for (int k = 0; k < T; ++k) {
            C3out[base + (size_t)b * T + k]                    = (float)preds[k];
            C3out[base + (size_t)BSZ * T + (size_t)b * T + k]  = (float)tg[k];
        }
    }
}

// ---------------------------------------------------------------------------
extern "C" void kernel_launch(void* const* d_in, const int* in_sizes, int n_in,
                              void* d_out, int out_size)
{
    const float* logits  = (const float*)d_in[0];   // [32,900,91]
    const float* pboxes  = (const float*)d_in[1];   // [32,900,4]
    const int*   tlabels = (const int*)  d_in[2];   // [32,30]
    const float* tboxes  = (const float*)d_in[3];   // [32,30,4]
    float* out = (float*)d_out;

    cost_kernel<<<BSZ * Q, 128>>>(logits, pboxes, tlabels, tboxes, out);

    const size_t smem =
        (size_t)T * Q * sizeof(float)            // costT   108000
        + (Q + 1) * sizeof(double) * 2           // v, minv  14416
        + 256 * sizeof(double)                   // rval      2048
        + (Q + 1) * sizeof(int) * 3              // p,way,used 10812
        + 256 * sizeof(int);                     // ridx      1024
    cudaFuncSetAttribute(lsa_kernel, cudaFuncAttributeMaxDynamicSharedMemorySize,
                         (int)smem);
    lsa_kernel<<<BSZ, 256, smem>>>(out);
}